// round 5
// baseline (speedup 1.0000x reference)
#include <cuda_runtime.h>
#include <math.h>

#define NN 50000
#define NE 800000
#define ET (NE + NN)
#define DI 128
#define DH 64
#define DOUT 40
#define SLOPE 0.2f
#define SCB 1024
#define NBLK 49            // ceil(50000/1024)

typedef unsigned long long u64;

__device__ __forceinline__ u64 pack2(float lo, float hi) {
    u64 r; asm("mov.b64 %0,{%1,%2};" : "=l"(r) : "f"(lo), "f"(hi)); return r;
}
__device__ __forceinline__ float2 unpack2(u64 a) {
    float2 f; asm("mov.b64 {%0,%1}, %2;" : "=f"(f.x), "=f"(f.y) : "l"(a)); return f;
}
__device__ __forceinline__ void fma2(u64& a, u64 x, u64 w) {
    asm("fma.rn.f32x2 %0, %1, %2, %0;" : "+l"(a) : "l"(x), "l"(w));
}
__device__ __forceinline__ void mul2(u64& a, u64 b) {
    asm("mul.rn.f32x2 %0, %0, %1;" : "+l"(a) : "l"(b));
}

// ---------------- scratch ----------------
__device__ float g_h[NN * DH];
__device__ float g_as[NN];
__device__ float g_ad[NN];
__device__ float g_h1o[NN * DH];
__device__ int   g_deg[NN];
__device__ int   g_rowptr[NN + 1];
__device__ int   g_pos[NN];
__device__ int   g_bsum[NBLK];
__device__ int   g_esrc[ET];

// ---------------- CSR build ----------------
// t < NE/4: 4 regular edges (int4). else: one self loop.
__global__ void hist_kernel(const int* __restrict__ ei) {
    int t = blockIdx.x * blockDim.x + threadIdx.x;
    if (t < NE / 4) {
        int4 d4 = *(const int4*)&ei[NE + t * 4];
        atomicAdd(&g_deg[d4.x], 1);
        atomicAdd(&g_deg[d4.y], 1);
        atomicAdd(&g_deg[d4.z], 1);
        atomicAdd(&g_deg[d4.w], 1);
    } else {
        int n = t - NE / 4;
        if (n < NN) atomicAdd(&g_deg[n], 1);
    }
}

__global__ void scan_local_kernel() {
    __shared__ int wsum[32];
    int t = threadIdx.x, lane = t & 31, wid = t >> 5;
    int i = blockIdx.x * SCB + t;
    int v = (i < NN) ? g_deg[i] : 0;
    int sc = v;
#pragma unroll
    for (int off = 1; off < 32; off <<= 1) {
        int u = __shfl_up_sync(0xffffffffu, sc, off);
        if (lane >= off) sc += u;
    }
    if (lane == 31) wsum[wid] = sc;
    __syncthreads();
    if (wid == 0) {
        int w0 = wsum[lane];
        int s = w0;
#pragma unroll
        for (int off = 1; off < 32; off <<= 1) {
            int u = __shfl_up_sync(0xffffffffu, s, off);
            if (lane >= off) s += u;
        }
        wsum[lane] = s - w0;
    }
    __syncthreads();
    int ex = sc - v + wsum[wid];
    if (i < NN) g_rowptr[i] = ex;
    if (t == SCB - 1) g_bsum[blockIdx.x] = ex + v;
}

// merged: compute block prefix from g_bsum in-kernel, add, write pos; set rowptr[NN]
__global__ void add_off_kernel() {
    __shared__ int sh[2];
    int t = threadIdx.x, bid = blockIdx.x;
    if (t < 32) {
        int a = (t < NBLK) ? g_bsum[t] : 0;
        int b = (t + 32 < NBLK) ? g_bsum[t + 32] : 0;
        int pa = ((t < bid) ? a : 0) + ((t + 32 < bid) ? b : 0);
        int ta = a + b;
#pragma unroll
        for (int off = 16; off; off >>= 1) {
            pa += __shfl_xor_sync(0xffffffffu, pa, off);
            ta += __shfl_xor_sync(0xffffffffu, ta, off);
        }
        if (t == 0) { sh[0] = pa; sh[1] = ta; }
    }
    __syncthreads();
    int pre = sh[0];
    int i = bid * SCB + t;
    if (i < NN) {
        int r = g_rowptr[i] + pre;
        g_rowptr[i] = r;
        g_pos[i] = r;
    }
    if (bid == NBLK - 1 && t == 0) g_rowptr[NN] = sh[1];
}

__global__ void scatter_kernel(const int* __restrict__ ei) {
    int t = blockIdx.x * blockDim.x + threadIdx.x;
    if (t < NE / 4) {
        int4 s4 = *(const int4*)&ei[t * 4];
        int4 d4 = *(const int4*)&ei[NE + t * 4];
        g_esrc[atomicAdd(&g_pos[d4.x], 1)] = s4.x;
        g_esrc[atomicAdd(&g_pos[d4.y], 1)] = s4.y;
        g_esrc[atomicAdd(&g_pos[d4.z], 1)] = s4.z;
        g_esrc[atomicAdd(&g_pos[d4.w], 1)] = s4.w;
    } else {
        int n = t - NE / 4;
        if (n < NN) g_esrc[atomicAdd(&g_pos[n], 1)] = n;
    }
}

// ---------------- f32x2 GEMM: H = X @ W ----------------
// 64-node x Dout tile; thread = 4 nodes x 4 cols (8 f32x2 accumulators).
// smem: sxd[Din][64] x-values duplicated as {x,x} pairs; sw[Din][Dout] plain.
template <int Din, int Dout, bool USE_X>
__global__ void gemm_kernel(const float* __restrict__ X, const float* __restrict__ W) {
    extern __shared__ char smem[];
    u64*   sxd = (u64*)smem;
    float* sw  = (float*)(smem + (size_t)Din * 64 * sizeof(u64));
    const float* src = USE_X ? X : g_h1o;
    const int nthr = (Dout / 4) * 16;
    int tid = threadIdx.x;
    int base = blockIdx.x * 64;

    for (int i = tid; i < 64 * (Din / 4); i += nthr) {
        int ln = i / (Din / 4);
        int k4 = (i % (Din / 4)) * 4;
        int node = base + ln;
        float4 v = (node < NN) ? ((const float4*)src)[(size_t)node * (Din / 4) + (k4 >> 2)]
                               : make_float4(0.f, 0.f, 0.f, 0.f);
        sxd[(k4 + 0) * 64 + ln] = pack2(v.x, v.x);
        sxd[(k4 + 1) * 64 + ln] = pack2(v.y, v.y);
        sxd[(k4 + 2) * 64 + ln] = pack2(v.z, v.z);
        sxd[(k4 + 3) * 64 + ln] = pack2(v.w, v.w);
    }
    for (int i = tid; i < Din * Dout / 4; i += nthr)
        ((float4*)sw)[i] = ((const float4*)W)[i];
    __syncthreads();

    int cg = tid % (Dout / 4);
    int ng = tid / (Dout / 4);
    u64 acc[4][2];
#pragma unroll
    for (int n = 0; n < 4; n++) { acc[n][0] = 0ull; acc[n][1] = 0ull; }

#pragma unroll 8
    for (int k = 0; k < Din; k++) {
        const u64* xr = &sxd[k * 64 + ng * 4];
        u64 x0 = xr[0], x1 = xr[1], x2 = xr[2], x3 = xr[3];
        const u64* wr = (const u64*)&sw[k * Dout + cg * 4];
        u64 w0 = wr[0], w1 = wr[1];
        fma2(acc[0][0], x0, w0); fma2(acc[0][1], x0, w1);
        fma2(acc[1][0], x1, w0); fma2(acc[1][1], x1, w1);
        fma2(acc[2][0], x2, w0); fma2(acc[2][1], x2, w1);
        fma2(acc[3][0], x3, w0); fma2(acc[3][1], x3, w1);
    }
#pragma unroll
    for (int n = 0; n < 4; n++) {
        int node = base + ng * 4 + n;
        if (node < NN) {
            *(u64*)&g_h[(size_t)node * Dout + cg * 4]     = acc[n][0];
            *(u64*)&g_h[(size_t)node * Dout + cg * 4 + 2] = acc[n][1];
        }
    }
}

// ---------------- per-node attention dots ----------------
template <int D>
__global__ void att_kernel(const float* __restrict__ asrc, const float* __restrict__ adst) {
    int warp = (blockIdx.x * blockDim.x + threadIdx.x) >> 5;
    int lane = threadIdx.x & 31;
    if (warp >= NN) return;
    float sa = 0.f, sd = 0.f;
#pragma unroll
    for (int d = lane; d < D; d += 32) {
        float h = g_h[(size_t)warp * D + d];
        sa += h * asrc[d];
        sd += h * adst[d];
    }
#pragma unroll
    for (int off = 16; off; off >>= 1) {
        sa += __shfl_down_sync(0xffffffffu, sa, off);
        sd += __shfl_down_sync(0xffffffffu, sd, off);
    }
    if (lane == 0) { g_as[warp] = sa; g_ad[warp] = sd; }
}

// ---------------- fused online-softmax aggregation (+epilogue) ----------------
template <int D, bool FINAL>
__global__ void agg_kernel(const float* __restrict__ b, float* __restrict__ out) {
    __shared__ float sp_p[8][32];
    __shared__ int   sp_s[8][32];
    int wl = threadIdx.x >> 5;
    int w = (blockIdx.x * blockDim.x + threadIdx.x) >> 5;
    int lane = threadIdx.x & 31;
    if (w >= NN) return;
    int beg = g_rowptr[w];
    int end = g_rowptr[w + 1];
    float ad_n = g_ad[w];

    float m = -INFINITY;
    float ssum = 0.f;
    u64 a = 0ull;

    for (int j0 = beg; j0 < end; j0 += 32) {
        int j = j0 + lane;
        int s = 0;
        float e = -INFINITY;
        if (j < end) {
            s = g_esrc[j];
            e = g_as[s] + ad_n;
            e = e > 0.f ? e : SLOPE * e;
        }
        float tm = e;
#pragma unroll
        for (int off = 16; off; off >>= 1) tm = fmaxf(tm, __shfl_xor_sync(0xffffffffu, tm, off));
        float mnew = fmaxf(m, tm);
        float scale = __expf(m - mnew);
        ssum *= scale;
        mul2(a, pack2(scale, scale));
        m = mnew;

        float p = (j < end) ? __expf(e - m) : 0.f;
        ssum += p;
        sp_p[wl][lane] = p;
        sp_s[wl][lane] = s;
        __syncwarp();
        int cnt = min(32, end - j0);
        if (lane < D / 2) {
#pragma unroll 4
            for (int k = 0; k < cnt; k++) {
                float pk = sp_p[wl][k];
                int   sk = sp_s[wl][k];
                u64 hv = *(const u64*)&g_h[(size_t)sk * D + 2 * lane];
                fma2(a, hv, pack2(pk, pk));
            }
        }
        __syncwarp();
    }
#pragma unroll
    for (int off = 16; off; off >>= 1) ssum += __shfl_xor_sync(0xffffffffu, ssum, off);
    float inv = 1.f / (ssum + 1e-16f);
    float2 av = unpack2(a);

    if (!FINAL) {
        float v0 = av.x * inv + b[2 * lane];
        float v1 = av.y * inv + b[2 * lane + 1];
        float2 o;
        o.x = v0 > 0.f ? v0 : 0.f;
        o.y = v1 > 0.f ? v1 : 0.f;
        ((float2*)g_h1o)[(size_t)w * (D / 2) + lane] = o;
    } else {
        float va = -INFINITY, vb = -INFINITY;
        if (lane < D / 2) {
            va = av.x * inv + b[2 * lane];
            vb = av.y * inv + b[2 * lane + 1];
        }
        float mx = fmaxf(va, vb);
#pragma unroll
        for (int off = 16; off; off >>= 1) mx = fmaxf(mx, __shfl_xor_sync(0xffffffffu, mx, off));
        float se = (lane < D / 2) ? (__expf(va - mx) + __expf(vb - mx)) : 0.f;
#pragma unroll
        for (int off = 16; off; off >>= 1) se += __shfl_xor_sync(0xffffffffu, se, off);
        float lse = mx + logf(se);
        if (lane < D / 2) {
            float2 o;
            o.x = va - lse;
            o.y = vb - lse;
            ((float2*)out)[(size_t)w * (D / 2) + lane] = o;
        }
    }
}

extern "C" void kernel_launch(void* const* d_in, const int* in_sizes, int n_in,
                              void* d_out, int out_size) {
    const float* x   = (const float*)d_in[0];
    const int*   ei  = (const int*)d_in[1];
    const float* W1  = (const float*)d_in[2];
    const float* as1 = (const float*)d_in[3];
    const float* ad1 = (const float*)d_in[4];
    const float* b1  = (const float*)d_in[5];
    const float* W2  = (const float*)d_in[6];
    const float* as2 = (const float*)d_in[7];
    const float* ad2 = (const float*)d_in[8];
    const float* b2  = (const float*)d_in[9];
    float* out = (float*)d_out;

    const int TB = 256;
    int grid_edges = (NE / 4 + NN + TB - 1) / TB;
    int grid_warp_nodes = (NN * 32 + TB - 1) / TB;
    int grid_nodes64 = (NN + 63) / 64;

    const int SM1 = DI * 64 * 8 + DI * DH * 4;     // 98304
    const int SM2 = DH * 64 * 8 + DH * DOUT * 4;   // 43008
    cudaFuncSetAttribute(gemm_kernel<DI, DH, true>,
                         cudaFuncAttributeMaxDynamicSharedMemorySize, SM1);
    cudaFuncSetAttribute(gemm_kernel<DH, DOUT, false>,
                         cudaFuncAttributeMaxDynamicSharedMemorySize, SM2);

    void* degPtr = nullptr;
    cudaGetSymbolAddress(&degPtr, g_deg);

    // ---------------- CSR build ----------------
    cudaMemsetAsync(degPtr, 0, NN * sizeof(int));
    hist_kernel<<<grid_edges, TB>>>(ei);
    scan_local_kernel<<<NBLK, SCB>>>();
    add_off_kernel<<<NBLK, SCB>>>();
    scatter_kernel<<<grid_edges, TB>>>(ei);

    // ---------------- layer 1 ----------------
    gemm_kernel<DI, DH, true><<<grid_nodes64, (DH / 4) * 16, SM1>>>(x, W1);
    att_kernel<DH><<<grid_warp_nodes, TB>>>(as1, ad1);
    agg_kernel<DH, false><<<grid_warp_nodes, TB>>>(b1, nullptr);

    // ---------------- layer 2 ----------------
    gemm_kernel<DH, DOUT, false><<<grid_nodes64, (DOUT / 4) * 16, SM2>>>(nullptr, W2);
    att_kernel<DOUT><<<grid_warp_nodes, TB>>>(as2, ad2);
    agg_kernel<DOUT, true><<<grid_warp_nodes, TB>>>(b2, out);
}

// round 6
// speedup vs baseline: 1.1770x; 1.1770x over previous
#include <cuda_runtime.h>
#include <cuda_fp16.h>
#include <math.h>

#define NN 50000
#define NE 800000
#define ET (NE + NN)
#define DI 128
#define DH 64
#define DOUT 40
#define SLOPE 0.2f
#define SCB 1024
#define NBLK 49            // ceil(50000/1024)

// ---------------- scratch ----------------
__device__ float  g_h[NN * DH];
__device__ __half2 g_h16[NN * (DH / 2)];
__device__ float  g_as[NN];
__device__ float  g_ad[NN];
__device__ float  g_h1o[NN * DH];
__device__ int    g_deg[NN];
__device__ int    g_rowptr[NN + 1];
__device__ int    g_pos[NN];
__device__ int    g_bsum[NBLK];
__device__ int    g_esrc[ET];

// ---------------- CSR build ----------------
// 8 edges per thread (front-batched loads -> high atomic MLP); tail threads do self loops.
__global__ void hist_kernel(const int* __restrict__ ei) {
    int t = blockIdx.x * blockDim.x + threadIdx.x;
    if (t < NE / 8) {
        int4 a = *(const int4*)&ei[NE + t * 8];
        int4 b = *(const int4*)&ei[NE + t * 8 + 4];
        atomicAdd(&g_deg[a.x], 1);
        atomicAdd(&g_deg[a.y], 1);
        atomicAdd(&g_deg[a.z], 1);
        atomicAdd(&g_deg[a.w], 1);
        atomicAdd(&g_deg[b.x], 1);
        atomicAdd(&g_deg[b.y], 1);
        atomicAdd(&g_deg[b.z], 1);
        atomicAdd(&g_deg[b.w], 1);
    } else {
        int n = t - NE / 8;
        if (n < NN) atomicAdd(&g_deg[n], 1);
    }
}

__global__ void scan_local_kernel() {
    __shared__ int wsum[32];
    int t = threadIdx.x, lane = t & 31, wid = t >> 5;
    int i = blockIdx.x * SCB + t;
    int v = (i < NN) ? g_deg[i] : 0;
    int sc = v;
#pragma unroll
    for (int off = 1; off < 32; off <<= 1) {
        int u = __shfl_up_sync(0xffffffffu, sc, off);
        if (lane >= off) sc += u;
    }
    if (lane == 31) wsum[wid] = sc;
    __syncthreads();
    if (wid == 0) {
        int w0 = wsum[lane];
        int s = w0;
#pragma unroll
        for (int off = 1; off < 32; off <<= 1) {
            int u = __shfl_up_sync(0xffffffffu, s, off);
            if (lane >= off) s += u;
        }
        wsum[lane] = s - w0;
    }
    __syncthreads();
    int ex = sc - v + wsum[wid];
    if (i < NN) g_rowptr[i] = ex;
    if (t == SCB - 1) g_bsum[blockIdx.x] = ex + v;
}

__global__ void add_off_kernel() {
    __shared__ int sh[2];
    int t = threadIdx.x, bid = blockIdx.x;
    if (t < 32) {
        int a = (t < NBLK) ? g_bsum[t] : 0;
        int b = (t + 32 < NBLK) ? g_bsum[t + 32] : 0;
        int pa = ((t < bid) ? a : 0) + ((t + 32 < bid) ? b : 0);
        int ta = a + b;
#pragma unroll
        for (int off = 16; off; off >>= 1) {
            pa += __shfl_xor_sync(0xffffffffu, pa, off);
            ta += __shfl_xor_sync(0xffffffffu, ta, off);
        }
        if (t == 0) { sh[0] = pa; sh[1] = ta; }
    }
    __syncthreads();
    int pre = sh[0];
    int i = bid * SCB + t;
    if (i < NN) {
        int r = g_rowptr[i] + pre;
        g_rowptr[i] = r;
        g_pos[i] = r;
    }
    if (bid == NBLK - 1 && t == 0) g_rowptr[NN] = sh[1];
}

__global__ void scatter_kernel(const int* __restrict__ ei) {
    int t = blockIdx.x * blockDim.x + threadIdx.x;
    if (t < NE / 8) {
        int4 s0 = *(const int4*)&ei[t * 8];
        int4 s1 = *(const int4*)&ei[t * 8 + 4];
        int4 d0 = *(const int4*)&ei[NE + t * 8];
        int4 d1 = *(const int4*)&ei[NE + t * 8 + 4];
        int i0 = atomicAdd(&g_pos[d0.x], 1);
        int i1 = atomicAdd(&g_pos[d0.y], 1);
        int i2 = atomicAdd(&g_pos[d0.z], 1);
        int i3 = atomicAdd(&g_pos[d0.w], 1);
        int i4 = atomicAdd(&g_pos[d1.x], 1);
        int i5 = atomicAdd(&g_pos[d1.y], 1);
        int i6 = atomicAdd(&g_pos[d1.z], 1);
        int i7 = atomicAdd(&g_pos[d1.w], 1);
        g_esrc[i0] = s0.x; g_esrc[i1] = s0.y; g_esrc[i2] = s0.z; g_esrc[i3] = s0.w;
        g_esrc[i4] = s1.x; g_esrc[i5] = s1.y; g_esrc[i6] = s1.z; g_esrc[i7] = s1.w;
    } else {
        int n = t - NE / 8;
        if (n < NN) g_esrc[atomicAdd(&g_pos[n], 1)] = n;
    }
}

// ---------------- dense GEMM: H = X @ W (round-3 design, measured good) ----------------
template <int Din, int Dout, bool USE_X>
__global__ void gemm_kernel(const float* __restrict__ X, const float* __restrict__ W) {
    __shared__ float sx[32 * Din];
    const float* src = USE_X ? X : g_h1o;
    int base = blockIdx.x * 32;
    int tid = threadIdx.x;
    const int nthr = Dout * 4;

    for (int i = tid; i < 32 * (Din / 4); i += nthr) {
        int node = base + i / (Din / 4);
        float4 v = (node < NN) ? ((const float4*)src)[(size_t)node * (Din / 4) + (i % (Din / 4))]
                               : make_float4(0.f, 0.f, 0.f, 0.f);
        ((float4*)sx)[i] = v;
    }
    __syncthreads();

    int j = tid % Dout;
    int n0 = tid / Dout;
    float acc[8];
#pragma unroll
    for (int i = 0; i < 8; i++) acc[i] = 0.f;

    for (int k = 0; k < Din; k += 4) {
        float w0 = W[(k + 0) * Dout + j];
        float w1 = W[(k + 1) * Dout + j];
        float w2 = W[(k + 2) * Dout + j];
        float w3 = W[(k + 3) * Dout + j];
#pragma unroll
        for (int i = 0; i < 8; i++) {
            int node = n0 + i * 4;
            float4 xv = ((const float4*)sx)[node * (Din / 4) + (k >> 2)];
            acc[i] += xv.x * w0 + xv.y * w1 + xv.z * w2 + xv.w * w3;
        }
    }
#pragma unroll
    for (int i = 0; i < 8; i++) {
        int node = base + n0 + i * 4;
        if (node < NN) g_h[(size_t)node * Dout + j] = acc[i];
    }
}

// ---------------- attention dots + fp16 conversion (fused; streams g_h once) --------
template <int D>
__global__ void att_kernel(const float* __restrict__ asrc, const float* __restrict__ adst) {
    int warp = (blockIdx.x * blockDim.x + threadIdx.x) >> 5;
    int lane = threadIdx.x & 31;
    if (warp >= NN) return;
    float sa = 0.f, sd = 0.f;
    float2 hv = make_float2(0.f, 0.f);
    if (lane < D / 2) {
        hv = ((const float2*)g_h)[(size_t)warp * (D / 2) + lane];
        sa = hv.x * asrc[2 * lane] + hv.y * asrc[2 * lane + 1];
        sd = hv.x * adst[2 * lane] + hv.y * adst[2 * lane + 1];
        g_h16[(size_t)warp * (D / 2) + lane] = __float22half2_rn(hv);
    }
#pragma unroll
    for (int off = 16; off; off >>= 1) {
        sa += __shfl_down_sync(0xffffffffu, sa, off);
        sd += __shfl_down_sync(0xffffffffu, sd, off);
    }
    if (lane == 0) { g_as[warp] = sa; g_ad[warp] = sd; }
}

// ---------------- fused segment softmax + aggregation (+epilogue) ----------------
// warp per dst node; two-pass softmax; fp16 feature gather (half the L2 bytes).
template <int D, bool FINAL>
__global__ void agg_kernel(const float* __restrict__ b, float* __restrict__ out) {
    __shared__ float sp_p[8][32];
    __shared__ int   sp_s[8][32];
    int wl = threadIdx.x >> 5;
    int w = (blockIdx.x * blockDim.x + threadIdx.x) >> 5;
    int lane = threadIdx.x & 31;
    if (w >= NN) return;
    int beg = g_rowptr[w];
    int end = g_rowptr[w + 1];
    float ad_n = g_ad[w];

    // pass 1: segment max
    float m = -INFINITY;
    for (int j = beg + lane; j < end; j += 32) {
        float e = g_as[g_esrc[j]] + ad_n;
        e = e > 0.f ? e : SLOPE * e;
        m = fmaxf(m, e);
    }
#pragma unroll
    for (int off = 16; off; off >>= 1) m = fmaxf(m, __shfl_xor_sync(0xffffffffu, m, off));

    // pass 2: tiles of 32 edges: p -> smem, then broadcast-aggregate fp16 rows
    float ssum = 0.f;
    float ax = 0.f, ay = 0.f;
    for (int j0 = beg; j0 < end; j0 += 32) {
        int j = j0 + lane;
        float p = 0.f;
        int s = 0;
        if (j < end) {
            s = g_esrc[j];
            float e = g_as[s] + ad_n;
            e = e > 0.f ? e : SLOPE * e;
            p = __expf(e - m);
        }
        ssum += p;
        sp_p[wl][lane] = p;
        sp_s[wl][lane] = s;
        __syncwarp();
        int cnt = min(32, end - j0);
        if (lane < D / 2) {
#pragma unroll 4
            for (int k = 0; k < cnt; k++) {
                float pk = sp_p[wl][k];
                int   sk = sp_s[wl][k];
                float2 hv = __half22float2(g_h16[(size_t)sk * (D / 2) + lane]);
                ax += pk * hv.x;
                ay += pk * hv.y;
            }
        }
        __syncwarp();
    }
#pragma unroll
    for (int off = 16; off; off >>= 1) ssum += __shfl_xor_sync(0xffffffffu, ssum, off);
    float inv = 1.f / (ssum + 1e-16f);

    if (!FINAL) {
        float v0 = ax * inv + b[2 * lane];
        float v1 = ay * inv + b[2 * lane + 1];
        float2 o;
        o.x = v0 > 0.f ? v0 : 0.f;
        o.y = v1 > 0.f ? v1 : 0.f;
        ((float2*)g_h1o)[(size_t)w * (D / 2) + lane] = o;
    } else {
        float va = -INFINITY, vb = -INFINITY;
        if (lane < D / 2) {
            va = ax * inv + b[2 * lane];
            vb = ay * inv + b[2 * lane + 1];
        }
        float mx = fmaxf(va, vb);
#pragma unroll
        for (int off = 16; off; off >>= 1) mx = fmaxf(mx, __shfl_xor_sync(0xffffffffu, mx, off));
        float se = (lane < D / 2) ? (__expf(va - mx) + __expf(vb - mx)) : 0.f;
#pragma unroll
        for (int off = 16; off; off >>= 1) se += __shfl_xor_sync(0xffffffffu, se, off);
        float lse = mx + logf(se);
        if (lane < D / 2) {
            float2 o;
            o.x = va - lse;
            o.y = vb - lse;
            ((float2*)out)[(size_t)w * (D / 2) + lane] = o;
        }
    }
}

extern "C" void kernel_launch(void* const* d_in, const int* in_sizes, int n_in,
                              void* d_out, int out_size) {
    const float* x   = (const float*)d_in[0];
    const int*   ei  = (const int*)d_in[1];
    const float* W1  = (const float*)d_in[2];
    const float* as1 = (const float*)d_in[3];
    const float* ad1 = (const float*)d_in[4];
    const float* b1  = (const float*)d_in[5];
    const float* W2  = (const float*)d_in[6];
    const float* as2 = (const float*)d_in[7];
    const float* ad2 = (const float*)d_in[8];
    const float* b2  = (const float*)d_in[9];
    float* out = (float*)d_out;

    const int TB = 256;
    int grid_edges = (NE / 8 + NN + TB - 1) / TB;
    int grid_warp_nodes = (NN * 32 + TB - 1) / TB;
    int grid_nodes32 = (NN + 31) / 32;

    void* degPtr = nullptr;
    cudaGetSymbolAddress(&degPtr, g_deg);

    // ---------------- CSR build ----------------
    cudaMemsetAsync(degPtr, 0, NN * sizeof(int));
    hist_kernel<<<grid_edges, TB>>>(ei);
    scan_local_kernel<<<NBLK, SCB>>>();
    add_off_kernel<<<NBLK, SCB>>>();
    scatter_kernel<<<grid_edges, TB>>>(ei);

    // ---------------- layer 1 ----------------
    gemm_kernel<DI, DH, true><<<grid_nodes32, DH * 4>>>(x, W1);
    att_kernel<DH><<<grid_warp_nodes, TB>>>(as1, ad1);
    agg_kernel<DH, false><<<grid_warp_nodes, TB>>>(b1, nullptr);

    // ---------------- layer 2 ----------------
    gemm_kernel<DH, DOUT, false><<<grid_nodes32, DOUT * 4>>>(nullptr, W2);
    att_kernel<DOUT><<<grid_warp_nodes, TB>>>(as2, ad2);
    agg_kernel<DOUT, true><<<grid_warp_nodes, TB>>>(b2, out);
}

// round 7
// speedup vs baseline: 1.1931x; 1.0137x over previous
#include <cuda_runtime.h>
#include <cuda_fp16.h>
#include <math.h>

#define NN 50000
#define NE 800000
#define ET (NE + NN)
#define DI 128
#define DH 64
#define DOUT 40
#define SLOPE 0.2f
#define SCB 1024
#define NBLK 49            // ceil(50000/1024)

// ---------------- scratch ----------------
__device__ float   g_h[NN * DH];
__device__ __half2 g_h16[NN * (DH / 2)];
__device__ float   g_as[NN];
__device__ float   g_ad[NN];
__device__ float   g_h1o[NN * DH];
__device__ int     g_deg[NN];
__device__ int     g_rowptr[NN + 1];
__device__ int     g_bsum[NBLK];
__device__ int     g_rank[ET];
__device__ int     g_esrc[ET];

// ---------------- CSR build ----------------
// hist also records each edge's within-destination rank (atomicAdd return value),
// so the scatter pass needs no atomics at all.
__global__ void hist_kernel(const int* __restrict__ ei) {
    int t = blockIdx.x * blockDim.x + threadIdx.x;
    if (t < NE / 8) {
        int4 a = *(const int4*)&ei[NE + t * 8];
        int4 b = *(const int4*)&ei[NE + t * 8 + 4];
        int r0 = atomicAdd(&g_deg[a.x], 1);
        int r1 = atomicAdd(&g_deg[a.y], 1);
        int r2 = atomicAdd(&g_deg[a.z], 1);
        int r3 = atomicAdd(&g_deg[a.w], 1);
        int r4 = atomicAdd(&g_deg[b.x], 1);
        int r5 = atomicAdd(&g_deg[b.y], 1);
        int r6 = atomicAdd(&g_deg[b.z], 1);
        int r7 = atomicAdd(&g_deg[b.w], 1);
        *(int4*)&g_rank[t * 8]     = make_int4(r0, r1, r2, r3);
        *(int4*)&g_rank[t * 8 + 4] = make_int4(r4, r5, r6, r7);
    } else {
        int n = t - NE / 8;
        if (n < NN) g_rank[NE + n] = atomicAdd(&g_deg[n], 1);
    }
}

__global__ void scan_local_kernel() {
    __shared__ int wsum[32];
    int t = threadIdx.x, lane = t & 31, wid = t >> 5;
    int i = blockIdx.x * SCB + t;
    int v = (i < NN) ? g_deg[i] : 0;
    int sc = v;
#pragma unroll
    for (int off = 1; off < 32; off <<= 1) {
        int u = __shfl_up_sync(0xffffffffu, sc, off);
        if (lane >= off) sc += u;
    }
    if (lane == 31) wsum[wid] = sc;
    __syncthreads();
    if (wid == 0) {
        int w0 = wsum[lane];
        int s = w0;
#pragma unroll
        for (int off = 1; off < 32; off <<= 1) {
            int u = __shfl_up_sync(0xffffffffu, s, off);
            if (lane >= off) s += u;
        }
        wsum[lane] = s - w0;
    }
    __syncthreads();
    int ex = sc - v + wsum[wid];
    if (i < NN) g_rowptr[i] = ex;
    if (t == SCB - 1) g_bsum[blockIdx.x] = ex + v;
}

__global__ void add_off_kernel() {
    __shared__ int sh[2];
    int t = threadIdx.x, bid = blockIdx.x;
    if (t < 32) {
        int a = (t < NBLK) ? g_bsum[t] : 0;
        int b = (t + 32 < NBLK) ? g_bsum[t + 32] : 0;
        int pa = ((t < bid) ? a : 0) + ((t + 32 < bid) ? b : 0);
        int ta = a + b;
#pragma unroll
        for (int off = 16; off; off >>= 1) {
            pa += __shfl_xor_sync(0xffffffffu, pa, off);
            ta += __shfl_xor_sync(0xffffffffu, ta, off);
        }
        if (t == 0) { sh[0] = pa; sh[1] = ta; }
    }
    __syncthreads();
    int pre = sh[0];
    int i = bid * SCB + t;
    if (i < NN) g_rowptr[i] += pre;
    if (bid == NBLK - 1 && t == 0) g_rowptr[NN] = sh[1];
}

// atomic-free scatter: pos = rowptr[dst] + rank
__global__ void scatter_kernel(const int* __restrict__ ei) {
    int t = blockIdx.x * blockDim.x + threadIdx.x;
    if (t < NE / 8) {
        int4 s0 = *(const int4*)&ei[t * 8];
        int4 s1 = *(const int4*)&ei[t * 8 + 4];
        int4 d0 = *(const int4*)&ei[NE + t * 8];
        int4 d1 = *(const int4*)&ei[NE + t * 8 + 4];
        int4 r0 = *(const int4*)&g_rank[t * 8];
        int4 r1 = *(const int4*)&g_rank[t * 8 + 4];
        int p0 = g_rowptr[d0.x] + r0.x;
        int p1 = g_rowptr[d0.y] + r0.y;
        int p2 = g_rowptr[d0.z] + r0.z;
        int p3 = g_rowptr[d0.w] + r0.w;
        int p4 = g_rowptr[d1.x] + r1.x;
        int p5 = g_rowptr[d1.y] + r1.y;
        int p6 = g_rowptr[d1.z] + r1.z;
        int p7 = g_rowptr[d1.w] + r1.w;
        g_esrc[p0] = s0.x; g_esrc[p1] = s0.y; g_esrc[p2] = s0.z; g_esrc[p3] = s0.w;
        g_esrc[p4] = s1.x; g_esrc[p5] = s1.y; g_esrc[p6] = s1.z; g_esrc[p7] = s1.w;
    } else {
        int n = t - NE / 8;
        if (n < NN) g_esrc[g_rowptr[n] + g_rank[NE + n]] = n;
    }
}

// ---------------- dense GEMM: H = X @ W ----------------
template <int Din, int Dout, bool USE_X>
__global__ void gemm_kernel(const float* __restrict__ X, const float* __restrict__ W) {
    __shared__ float sx[32 * Din];
    const float* src = USE_X ? X : g_h1o;
    int base = blockIdx.x * 32;
    int tid = threadIdx.x;
    const int nthr = Dout * 4;

    for (int i = tid; i < 32 * (Din / 4); i += nthr) {
        int node = base + i / (Din / 4);
        float4 v = (node < NN) ? ((const float4*)src)[(size_t)node * (Din / 4) + (i % (Din / 4))]
                               : make_float4(0.f, 0.f, 0.f, 0.f);
        ((float4*)sx)[i] = v;
    }
    __syncthreads();

    int j = tid % Dout;
    int n0 = tid / Dout;
    float acc[8];
#pragma unroll
    for (int i = 0; i < 8; i++) acc[i] = 0.f;

    for (int k = 0; k < Din; k += 4) {
        float w0 = W[(k + 0) * Dout + j];
        float w1 = W[(k + 1) * Dout + j];
        float w2 = W[(k + 2) * Dout + j];
        float w3 = W[(k + 3) * Dout + j];
#pragma unroll
        for (int i = 0; i < 8; i++) {
            int node = n0 + i * 4;
            float4 xv = ((const float4*)sx)[node * (Din / 4) + (k >> 2)];
            acc[i] += xv.x * w0 + xv.y * w1 + xv.z * w2 + xv.w * w3;
        }
    }
#pragma unroll
    for (int i = 0; i < 8; i++) {
        int node = base + n0 + i * 4;
        if (node < NN) g_h[(size_t)node * Dout + j] = acc[i];
    }
}

// ---------------- attention dots + fp16 conversion (streams g_h once) --------
template <int D>
__global__ void att_kernel(const float* __restrict__ asrc, const float* __restrict__ adst) {
    int warp = (blockIdx.x * blockDim.x + threadIdx.x) >> 5;
    int lane = threadIdx.x & 31;
    if (warp >= NN) return;
    float sa = 0.f, sd = 0.f;
    if (lane < D / 2) {
        float2 hv = ((const float2*)g_h)[(size_t)warp * (D / 2) + lane];
        sa = hv.x * asrc[2 * lane] + hv.y * asrc[2 * lane + 1];
        sd = hv.x * adst[2 * lane] + hv.y * adst[2 * lane + 1];
        g_h16[(size_t)warp * (D / 2) + lane] = __float22half2_rn(hv);
    }
#pragma unroll
    for (int off = 16; off; off >>= 1) {
        sa += __shfl_down_sync(0xffffffffu, sa, off);
        sd += __shfl_down_sync(0xffffffffu, sd, off);
    }
    if (lane == 0) { g_as[warp] = sa; g_ad[warp] = sd; }
}

// ---------------- fused ONLINE-softmax aggregation (+epilogue) ----------------
// warp per dst node; single pass: tile max + rescale; fp16 gathers, unroll 8.
template <int D, bool FINAL>
__global__ void agg_kernel(const float* __restrict__ b, float* __restrict__ out) {
    __shared__ float sp_p[8][32];
    __shared__ int   sp_s[8][32];
    int wl = threadIdx.x >> 5;
    int w = (blockIdx.x * blockDim.x + threadIdx.x) >> 5;
    int lane = threadIdx.x & 31;
    if (w >= NN) return;
    int beg = g_rowptr[w];
    int end = g_rowptr[w + 1];
    float ad_n = g_ad[w];

    float m = -INFINITY;
    float ssum = 0.f;
    float ax = 0.f, ay = 0.f;

    for (int j0 = beg; j0 < end; j0 += 32) {
        int j = j0 + lane;
        int s = 0;
        float e = -INFINITY;
        if (j < end) {
            s = g_esrc[j];
            e = g_as[s] + ad_n;
            e = e > 0.f ? e : SLOPE * e;
        }
        float tm = e;
#pragma unroll
        for (int off = 16; off; off >>= 1) tm = fmaxf(tm, __shfl_xor_sync(0xffffffffu, tm, off));
        float mnew = fmaxf(m, tm);
        float scale = __expf(m - mnew);     // first tile: exp(-inf)=0
        ssum *= scale; ax *= scale; ay *= scale;
        m = mnew;

        float p = (j < end) ? __expf(e - m) : 0.f;
        ssum += p;
        sp_p[wl][lane] = p;
        sp_s[wl][lane] = s;
        __syncwarp();
        int cnt = min(32, end - j0);
        if (lane < D / 2) {
#pragma unroll 8
            for (int k = 0; k < cnt; k++) {
                float pk = sp_p[wl][k];
                int   sk = sp_s[wl][k];
                float2 hv = __half22float2(g_h16[(size_t)sk * (D / 2) + lane]);
                ax += pk * hv.x;
                ay += pk * hv.y;
            }
        }
        __syncwarp();
    }
#pragma unroll
    for (int off = 16; off; off >>= 1) ssum += __shfl_xor_sync(0xffffffffu, ssum, off);
    float inv = 1.f / (ssum + 1e-16f);

    if (!FINAL) {
        float v0 = ax * inv + b[2 * lane];
        float v1 = ay * inv + b[2 * lane + 1];
        float2 o;
        o.x = v0 > 0.f ? v0 : 0.f;
        o.y = v1 > 0.f ? v1 : 0.f;
        ((float2*)g_h1o)[(size_t)w * (D / 2) + lane] = o;
    } else {
        float va = -INFINITY, vb = -INFINITY;
        if (lane < D / 2) {
            va = ax * inv + b[2 * lane];
            vb = ay * inv + b[2 * lane + 1];
        }
        float mx = fmaxf(va, vb);
#pragma unroll
        for (int off = 16; off; off >>= 1) mx = fmaxf(mx, __shfl_xor_sync(0xffffffffu, mx, off));
        float se = (lane < D / 2) ? (__expf(va - mx) + __expf(vb - mx)) : 0.f;
#pragma unroll
        for (int off = 16; off; off >>= 1) se += __shfl_xor_sync(0xffffffffu, se, off);
        float lse = mx + logf(se);
        if (lane < D / 2) {
            float2 o;
            o.x = va - lse;
            o.y = vb - lse;
            ((float2*)out)[(size_t)w * (D / 2) + lane] = o;
        }
    }
}

extern "C" void kernel_launch(void* const* d_in, const int* in_sizes, int n_in,
                              void* d_out, int out_size) {
    const float* x   = (const float*)d_in[0];
    const int*   ei  = (const int*)d_in[1];
    const float* W1  = (const float*)d_in[2];
    const float* as1 = (const float*)d_in[3];
    const float* ad1 = (const float*)d_in[4];
    const float* b1  = (const float*)d_in[5];
    const float* W2  = (const float*)d_in[6];
    const float* as2 = (const float*)d_in[7];
    const float* ad2 = (const float*)d_in[8];
    const float* b2  = (const float*)d_in[9];
    float* out = (float*)d_out;

    const int TB = 256;
    int grid_edges = (NE / 8 + NN + TB - 1) / TB;
    int grid_warp_nodes = (NN * 32 + TB - 1) / TB;
    int grid_nodes32 = (NN + 31) / 32;

    void* degPtr = nullptr;
    cudaGetSymbolAddress(&degPtr, g_deg);

    // ---------------- CSR build ----------------
    cudaMemsetAsync(degPtr, 0, NN * sizeof(int));
    hist_kernel<<<grid_edges, TB>>>(ei);
    scan_local_kernel<<<NBLK, SCB>>>();
    add_off_kernel<<<NBLK, SCB>>>();
    scatter_kernel<<<grid_edges, TB>>>(ei);

    // ---------------- layer 1 ----------------
    gemm_kernel<DI, DH, true><<<grid_nodes32, DH * 4>>>(x, W1);
    att_kernel<DH><<<grid_warp_nodes, TB>>>(as1, ad1);
    agg_kernel<DH, false><<<grid_warp_nodes, TB>>>(b1, nullptr);

    // ---------------- layer 2 ----------------
    gemm_kernel<DH, DOUT, false><<<grid_nodes32, DOUT * 4>>>(nullptr, W2);
    att_kernel<DOUT><<<grid_warp_nodes, TB>>>(as2, ad2);
    agg_kernel<DOUT, true><<<grid_warp_nodes, TB>>>(b2, out);
}

// round 8
// speedup vs baseline: 1.3261x; 1.1115x over previous
#include <cuda_runtime.h>
#include <cuda_fp16.h>
#include <math.h>

#define NN 50000
#define NE 800000
#define ET (NE + NN)
#define DI 128
#define DH 64
#define DOUT 40
#define SLOPE 0.2f
#define SCB 1024
#define NBLK 49            // ceil(50000/1024)

// ---------------- scratch ----------------
__device__ __half2 g_h16[NN * (DH / 2)];
__device__ float   g_as[NN];
__device__ float   g_ad[NN];
__device__ float   g_h1o[NN * DH];
__device__ int     g_deg[NN];
__device__ int     g_rowptr[NN + 1];
__device__ int     g_bsum[NBLK];
__device__ int     g_rank[ET];
__device__ int     g_esrc[ET];

// ---------------- CSR build ----------------
__global__ void hist_kernel(const int* __restrict__ ei) {
    int t = blockIdx.x * blockDim.x + threadIdx.x;
    if (t < NE / 8) {
        int4 a = *(const int4*)&ei[NE + t * 8];
        int4 b = *(const int4*)&ei[NE + t * 8 + 4];
        int r0 = atomicAdd(&g_deg[a.x], 1);
        int r1 = atomicAdd(&g_deg[a.y], 1);
        int r2 = atomicAdd(&g_deg[a.z], 1);
        int r3 = atomicAdd(&g_deg[a.w], 1);
        int r4 = atomicAdd(&g_deg[b.x], 1);
        int r5 = atomicAdd(&g_deg[b.y], 1);
        int r6 = atomicAdd(&g_deg[b.z], 1);
        int r7 = atomicAdd(&g_deg[b.w], 1);
        *(int4*)&g_rank[t * 8]     = make_int4(r0, r1, r2, r3);
        *(int4*)&g_rank[t * 8 + 4] = make_int4(r4, r5, r6, r7);
    } else {
        int n = t - NE / 8;
        if (n < NN) g_rank[NE + n] = atomicAdd(&g_deg[n], 1);
    }
}

__global__ void scan_local_kernel() {
    __shared__ int wsum[32];
    int t = threadIdx.x, lane = t & 31, wid = t >> 5;
    int i = blockIdx.x * SCB + t;
    int v = (i < NN) ? g_deg[i] : 0;
    int sc = v;
#pragma unroll
    for (int off = 1; off < 32; off <<= 1) {
        int u = __shfl_up_sync(0xffffffffu, sc, off);
        if (lane >= off) sc += u;
    }
    if (lane == 31) wsum[wid] = sc;
    __syncthreads();
    if (wid == 0) {
        int w0 = wsum[lane];
        int s = w0;
#pragma unroll
        for (int off = 1; off < 32; off <<= 1) {
            int u = __shfl_up_sync(0xffffffffu, s, off);
            if (lane >= off) s += u;
        }
        wsum[lane] = s - w0;
    }
    __syncthreads();
    int ex = sc - v + wsum[wid];
    if (i < NN) g_rowptr[i] = ex;
    if (t == SCB - 1) g_bsum[blockIdx.x] = ex + v;
}

__global__ void add_off_kernel() {
    __shared__ int sh[2];
    int t = threadIdx.x, bid = blockIdx.x;
    if (t < 32) {
        int a = (t < NBLK) ? g_bsum[t] : 0;
        int b = (t + 32 < NBLK) ? g_bsum[t + 32] : 0;
        int pa = ((t < bid) ? a : 0) + ((t + 32 < bid) ? b : 0);
        int ta = a + b;
#pragma unroll
        for (int off = 16; off; off >>= 1) {
            pa += __shfl_xor_sync(0xffffffffu, pa, off);
            ta += __shfl_xor_sync(0xffffffffu, ta, off);
        }
        if (t == 0) { sh[0] = pa; sh[1] = ta; }
    }
    __syncthreads();
    int pre = sh[0];
    int i = bid * SCB + t;
    if (i < NN) g_rowptr[i] += pre;
    if (bid == NBLK - 1 && t == 0) g_rowptr[NN] = sh[1];
}

__global__ void scatter_kernel(const int* __restrict__ ei) {
    int t = blockIdx.x * blockDim.x + threadIdx.x;
    if (t < NE / 8) {
        int4 s0 = *(const int4*)&ei[t * 8];
        int4 s1 = *(const int4*)&ei[t * 8 + 4];
        int4 d0 = *(const int4*)&ei[NE + t * 8];
        int4 d1 = *(const int4*)&ei[NE + t * 8 + 4];
        int4 r0 = *(const int4*)&g_rank[t * 8];
        int4 r1 = *(const int4*)&g_rank[t * 8 + 4];
        g_esrc[g_rowptr[d0.x] + r0.x] = s0.x;
        g_esrc[g_rowptr[d0.y] + r0.y] = s0.y;
        g_esrc[g_rowptr[d0.z] + r0.z] = s0.z;
        g_esrc[g_rowptr[d0.w] + r0.w] = s0.w;
        g_esrc[g_rowptr[d1.x] + r1.x] = s1.x;
        g_esrc[g_rowptr[d1.y] + r1.y] = s1.y;
        g_esrc[g_rowptr[d1.z] + r1.z] = s1.z;
        g_esrc[g_rowptr[d1.w] + r1.w] = s1.w;
    } else {
        int n = t - NE / 8;
        if (n < NN) g_esrc[g_rowptr[n] + g_rank[NE + n]] = n;
    }
}

// ---------------- fused GEMM + att dots + fp16 convert ----------------
// H = X@W for a 32-node tile; epilogue stages H in smem, emits g_h16 + g_as/g_ad.
template <int Din, int Dout, bool USE_X>
__global__ void gemm_att_kernel(const float* __restrict__ X, const float* __restrict__ W,
                                const float* __restrict__ asrc, const float* __restrict__ adst) {
    __shared__ float sx[32 * Din];   // x tile, later reused as h tile (32*Dout <= 32*Din)
    const float* src = USE_X ? X : g_h1o;
    int base = blockIdx.x * 32;
    int tid = threadIdx.x;
    const int nthr = Dout * 4;

    for (int i = tid; i < 32 * (Din / 4); i += nthr) {
        int node = base + i / (Din / 4);
        float4 v = (node < NN) ? ((const float4*)src)[(size_t)node * (Din / 4) + (i % (Din / 4))]
                               : make_float4(0.f, 0.f, 0.f, 0.f);
        ((float4*)sx)[i] = v;
    }
    __syncthreads();

    int j = tid % Dout;
    int n0 = tid / Dout;
    float acc[8];
#pragma unroll
    for (int i = 0; i < 8; i++) acc[i] = 0.f;

    for (int k = 0; k < Din; k += 4) {
        float w0 = W[(k + 0) * Dout + j];
        float w1 = W[(k + 1) * Dout + j];
        float w2 = W[(k + 2) * Dout + j];
        float w3 = W[(k + 3) * Dout + j];
#pragma unroll
        for (int i = 0; i < 8; i++) {
            int node = n0 + i * 4;
            float4 xv = ((const float4*)sx)[node * (Din / 4) + (k >> 2)];
            acc[i] += xv.x * w0 + xv.y * w1 + xv.z * w2 + xv.w * w3;
        }
    }
    __syncthreads();              // everyone done reading sx

    float* hacc = sx;             // reuse as h tile [32][Dout]
#pragma unroll
    for (int i = 0; i < 8; i++) hacc[(n0 + i * 4) * Dout + j] = acc[i];
    __syncthreads();

    // fp16 conversion: coalesced half2 stores
    for (int idx = tid; idx < 32 * (Dout / 2); idx += nthr) {
        int node = idx / (Dout / 2), c = idx % (Dout / 2);
        if (base + node < NN) {
            float2 v = make_float2(hacc[node * Dout + 2 * c], hacc[node * Dout + 2 * c + 1]);
            g_h16[(size_t)(base + node) * (Dout / 2) + c] = __float22half2_rn(v);
        }
    }

    // att dots: warp per node from smem
    int wid = tid >> 5, lane = tid & 31, nw = nthr / 32;
    for (int node = wid; node < 32; node += nw) {
        float sa = 0.f, sd = 0.f;
        for (int c = lane; c < Dout; c += 32) {
            float h = hacc[node * Dout + c];
            sa += h * asrc[c];
            sd += h * adst[c];
        }
#pragma unroll
        for (int off = 16; off; off >>= 1) {
            sa += __shfl_down_sync(0xffffffffu, sa, off);
            sd += __shfl_down_sync(0xffffffffu, sd, off);
        }
        if (lane == 0 && base + node < NN) {
            g_as[base + node] = sa;
            g_ad[base + node] = sd;
        }
    }
}

// ---------------- fused online-softmax aggregation (+epilogue) ----------------
template <int D, bool FINAL>
__global__ void agg_kernel(const float* __restrict__ b, float* __restrict__ out) {
    __shared__ float sp_p[8][32];
    __shared__ int   sp_s[8][32];
    int wl = threadIdx.x >> 5;
    int w = (blockIdx.x * blockDim.x + threadIdx.x) >> 5;
    int lane = threadIdx.x & 31;
    if (w >= NN) return;
    int beg = g_rowptr[w];
    int end = g_rowptr[w + 1];
    float ad_n = g_ad[w];

    float m = -INFINITY;
    float ssum = 0.f;
    float ax = 0.f, ay = 0.f;

    for (int j0 = beg; j0 < end; j0 += 32) {
        int j = j0 + lane;
        int s = 0;
        float e = -INFINITY;
        if (j < end) {
            s = g_esrc[j];
            e = g_as[s] + ad_n;
            e = e > 0.f ? e : SLOPE * e;
        }
        float tm = e;
#pragma unroll
        for (int off = 16; off; off >>= 1) tm = fmaxf(tm, __shfl_xor_sync(0xffffffffu, tm, off));
        float mnew = fmaxf(m, tm);
        float scale = __expf(m - mnew);
        ssum *= scale; ax *= scale; ay *= scale;
        m = mnew;

        float p = (j < end) ? __expf(e - m) : 0.f;
        ssum += p;
        sp_p[wl][lane] = p;
        sp_s[wl][lane] = s;
        __syncwarp();
        int cnt = min(32, end - j0);
        if (lane < D / 2) {
#pragma unroll 8
            for (int k = 0; k < cnt; k++) {
                float pk = sp_p[wl][k];
                int   sk = sp_s[wl][k];
                float2 hv = __half22float2(g_h16[(size_t)sk * (D / 2) + lane]);
                ax += pk * hv.x;
                ay += pk * hv.y;
            }
        }
        __syncwarp();
    }
#pragma unroll
    for (int off = 16; off; off >>= 1) ssum += __shfl_xor_sync(0xffffffffu, ssum, off);
    float inv = 1.f / (ssum + 1e-16f);

    if (!FINAL) {
        float v0 = ax * inv + b[2 * lane];
        float v1 = ay * inv + b[2 * lane + 1];
        float2 o;
        o.x = v0 > 0.f ? v0 : 0.f;
        o.y = v1 > 0.f ? v1 : 0.f;
        ((float2*)g_h1o)[(size_t)w * (D / 2) + lane] = o;
    } else {
        float va = -INFINITY, vb = -INFINITY;
        if (lane < D / 2) {
            va = ax * inv + b[2 * lane];
            vb = ay * inv + b[2 * lane + 1];
        }
        float mx = fmaxf(va, vb);
#pragma unroll
        for (int off = 16; off; off >>= 1) mx = fmaxf(mx, __shfl_xor_sync(0xffffffffu, mx, off));
        float se = (lane < D / 2) ? (__expf(va - mx) + __expf(vb - mx)) : 0.f;
#pragma unroll
        for (int off = 16; off; off >>= 1) se += __shfl_xor_sync(0xffffffffu, se, off);
        float lse = mx + logf(se);
        if (lane < D / 2) {
            float2 o;
            o.x = va - lse;
            o.y = vb - lse;
            ((float2*)out)[(size_t)w * (D / 2) + lane] = o;
        }
    }
}

extern "C" void kernel_launch(void* const* d_in, const int* in_sizes, int n_in,
                              void* d_out, int out_size) {
    const float* x   = (const float*)d_in[0];
    const int*   ei  = (const int*)d_in[1];
    const float* W1  = (const float*)d_in[2];
    const float* as1 = (const float*)d_in[3];
    const float* ad1 = (const float*)d_in[4];
    const float* b1  = (const float*)d_in[5];
    const float* W2  = (const float*)d_in[6];
    const float* as2 = (const float*)d_in[7];
    const float* ad2 = (const float*)d_in[8];
    const float* b2  = (const float*)d_in[9];
    float* out = (float*)d_out;

    // one-time side-stream + events (created on first (non-capture) call;
    // captured graph topology is identical on every call)
    static cudaStream_t s2 = nullptr;
    static cudaEvent_t evFork = nullptr, evCSR = nullptr;
    if (!s2) {
        cudaStreamCreateWithFlags(&s2, cudaStreamNonBlocking);
        cudaEventCreateWithFlags(&evFork, cudaEventDisableTiming);
        cudaEventCreateWithFlags(&evCSR, cudaEventDisableTiming);
    }

    const int TB = 256;
    int grid_edges = (NE / 8 + NN + TB - 1) / TB;
    int grid_warp_nodes = (NN * 32 + TB - 1) / TB;
    int grid_nodes32 = (NN + 31) / 32;

    void* degPtr = nullptr;
    cudaGetSymbolAddress(&degPtr, g_deg);

    // fork: CSR build on s2, concurrent with layer-1 GEMM on the main stream
    cudaEventRecord(evFork, 0);
    cudaStreamWaitEvent(s2, evFork, 0);

    cudaMemsetAsync(degPtr, 0, NN * sizeof(int), s2);
    hist_kernel<<<grid_edges, TB, 0, s2>>>(ei);
    scan_local_kernel<<<NBLK, SCB, 0, s2>>>();
    add_off_kernel<<<NBLK, SCB, 0, s2>>>();
    scatter_kernel<<<grid_edges, TB, 0, s2>>>(ei);
    cudaEventRecord(evCSR, s2);

    // layer 1 GEMM (+att dots, fp16 convert) on main stream
    gemm_att_kernel<DI, DH, true><<<grid_nodes32, DH * 4>>>(x, W1, as1, ad1);

    // join: aggregation needs both CSR and h/as/ad
    cudaStreamWaitEvent(0, evCSR, 0);
    agg_kernel<DH, false><<<grid_warp_nodes, TB>>>(b1, nullptr);

    // layer 2
    gemm_att_kernel<DH, DOUT, false><<<grid_nodes32, DOUT * 4>>>(nullptr, W2, as2, ad2);
    agg_kernel<DOUT, true><<<grid_warp_nodes, TB>>>(b2, out);
}